// round 8
// baseline (speedup 1.0000x reference)
#include <cuda_runtime.h>
#include <cstdint>

#define NB 128
#define P  16
#define N_ATOMS_MAX 50000

// Scratch (device globals: allocation-free per harness rules)
__device__ float g_h[N_ATOMS_MAX * NB];
__device__ float g_agg[N_ATOMS_MAX * NB];
__device__ float g_t[N_ATOMS_MAX * NB];

// ---------------- helpers ----------------

__device__ __forceinline__ float sspf(float x) {
    float e = __expf(-fabsf(x));
    return fmaxf(x, 0.0f) + __logf(1.0f + e) - 0.69314718055994531f;
}
__device__ __forceinline__ unsigned long long pack2(float x, float y) {
    unsigned long long r; asm("mov.b64 %0, {%1, %2};" : "=l"(r) : "f"(x), "f"(y)); return r;
}
__device__ __forceinline__ unsigned long long dupf(float w) {
    unsigned long long r; asm("mov.b64 %0, {%1, %1};" : "=l"(r) : "f"(w)); return r;
}
__device__ __forceinline__ void unpack2(unsigned long long v, float& x, float& y) {
    asm("mov.b64 {%0, %1}, %2;" : "=f"(x), "=f"(y) : "l"(v));
}
__device__ __forceinline__ void fma2(unsigned long long& d,
                                     unsigned long long a, unsigned long long b) {
    asm("fma.rn.f32x2 %0, %1, %2, %3;" : "=l"(d) : "l"(a), "l"(b), "l"(d));
}
__device__ __forceinline__ void red4(float* p, float a, float b, float c, float d) {
    asm volatile("red.global.add.v4.f32 [%0], {%1,%2,%3,%4};"
                 :: "l"(p), "f"(a), "f"(b), "f"(c), "f"(d) : "memory");
}

// ---------------- zero ----------------
__global__ void zero_kernel(float4* __restrict__ p, int n4) {
    int i = blockIdx.x * blockDim.x + threadIdx.x;
    if (i < n4) p[i] = make_float4(0.f, 0.f, 0.f, 0.f);
}

// dummy launch to shift ncu's profiled slot onto pair_kernel
__global__ void dummy_kernel() {}

// ---------------- row GEMM: Y = [ssp](X @ W + b), K=N=128 ----------------
template <bool DOSSP>
__global__ __launch_bounds__(128, 2) void rowmm_kernel(
    const float* __restrict__ X, const float* __restrict__ W,
    const float* __restrict__ b, float* __restrict__ Y, int nrows) {
    const int j = threadIdx.x;
    float wr[NB];
#pragma unroll
    for (int k = 0; k < NB; k++) wr[k] = W[k * NB + j];
    const float bj = b[j];
    __shared__ __align__(16) float xsh[NB * 4];
    const int ngroups = (nrows + 3) / 4;
    for (int g = blockIdx.x; g < ngroups; g += gridDim.x) {
        const int row0 = g * 4;
        __syncthreads();
#pragma unroll
        for (int r = 0; r < 4; r++) {
            int row = row0 + r;
            xsh[j * 4 + r] = (row < nrows) ? X[row * NB + j] : 0.0f;
        }
        __syncthreads();
        unsigned long long a01 = pack2(bj, bj), a23 = a01;
        const ulonglong2* xs2 = (const ulonglong2*)xsh;
#pragma unroll
        for (int k = 0; k < NB; k++) {
            ulonglong2 uv = xs2[k];
            unsigned long long wd = dupf(wr[k]);
            fma2(a01, uv.x, wd);
            fma2(a23, uv.y, wd);
        }
        float y0, y1, y2, y3;
        unpack2(a01, y0, y1); unpack2(a23, y2, y3);
        if (DOSSP) { y0 = sspf(y0); y1 = sspf(y1); y2 = sspf(y2); y3 = sspf(y3); }
        float yv[4] = {y0, y1, y2, y3};
#pragma unroll
        for (int r = 0; r < 4; r++) {
            int row = row0 + r;
            if (row < nrows) Y[row * NB + j] = yv[r];
        }
    }
}

// ---------------- fused pair kernel: split-K, 256 threads, P=16 ----------------
// Thread (j = tid&127, half = tid>>7). half h owns k in [h*KH, h*KH+KH).
// stage1: partial u over 10 k's -> bufA/bufB; combine: ssp(sum) in-place -> bufA = u [j][p]
// stage2: partial w over 64 k's -> bufB/bufC; combine: (+bias)*rcut -> bufA = w [p][j]
// epilogue: warp wid handles pairs 2*wid, 2*wid+1; h prefetched into regs early.

__global__ __launch_bounds__(256, 2) void pair_kernel(
    const float* __restrict__ f_ij, const float* __restrict__ rcut,
    const float* __restrict__ Wf1, const float* __restrict__ bf1,
    const float* __restrict__ Wf2, const float* __restrict__ bf2,
    const int* __restrict__ idx_i, const int* __restrict__ idx_j,
    const float* __restrict__ h, float* __restrict__ agg, int npairs) {
    const int tid  = threadIdx.x;
    const int j    = tid & 127;
    const int half = tid >> 7;
    const int wid  = tid >> 5;
    const int lane = tid & 31;

    float w1r[10];
#pragma unroll
    for (int k = 0; k < 10; k++) w1r[k] = Wf1[(half * 10 + k) * NB + j];
    float w2r[64];
#pragma unroll
    for (int k = 0; k < 64; k++) w2r[k] = Wf2[(half * 64 + k) * NB + j];
    // biases folded into half-0 accumulator init
    const float b1 = (half == 0) ? bf1[j] : 0.0f;
    const float b2 = (half == 0) ? bf2[j] : 0.0f;

    __shared__ __align__(16) float fsh[20 * P];      // [k][p]
    __shared__ __align__(16) float bufA[NB * P];     // u [j][p]  ->  w [p][j]
    __shared__ __align__(16) float bufB[NB * P];
    __shared__ __align__(16) float bufC[NB * P];
    __shared__ int   iish[P];
    __shared__ int   ijsh[P];
    __shared__ float rcsh[P];

    float4* A4 = (float4*)bufA;
    float4* B4 = (float4*)bufB;
    float4* C4 = (float4*)bufC;

    const int niter = (npairs + P - 1) / P;
    for (int it = blockIdx.x; it < niter; it += gridDim.x) {
        const int base = it * P;
        __syncthreads();  // prev epilogue done before smem overwrite

        // --- tile loads: f (320 floats = 80 float4), idx, rcut ---
        if (tid < 80) {
            float4 fv;
            if (base + P <= npairs) {
                fv = ((const float4*)f_ij)[base * 5 + tid];
            } else {
                float t[4];
#pragma unroll
                for (int c = 0; c < 4; c++) {
                    int g = base * 20 + tid * 4 + c;
                    t[c] = (g < npairs * 20) ? f_ij[g] : 0.0f;
                }
                fv = make_float4(t[0], t[1], t[2], t[3]);
            }
            float tv[4] = {fv.x, fv.y, fv.z, fv.w};
#pragma unroll
            for (int c = 0; c < 4; c++) {
                int g = tid * 4 + c;          // 0..319
                int p = g / 20, k = g - p * 20;
                fsh[k * P + p] = tv[c];
            }
        }
        if (tid >= 128 && tid < 128 + P) {
            int p = tid - 128;
            int e = base + p;
            bool v = (e < npairs);
            iish[p] = v ? idx_i[e] : 0;
            ijsh[p] = v ? idx_j[e] : 0;
            rcsh[p] = v ? rcut[e] : 0.0f;
        }
        __syncthreads();

        // --- early h gather for epilogue (hides L2 latency under GEMM) ---
        const int p0 = wid * 2, p1 = p0 + 1;
        const int ii0 = iish[p0], ii1 = iish[p1];
        float4 hv0 = ((const float4*)(h + (size_t)ijsh[p0] * NB))[lane];
        float4 hv1 = ((const float4*)(h + (size_t)ijsh[p1] * NB))[lane];

        // --- stage 1 partial: 10 k's per half ---
        {
            unsigned long long acc[8];
            unsigned long long bi = pack2(b1, b1);
#pragma unroll
            for (int i = 0; i < 8; i++) acc[i] = bi;
            const ulonglong2* fs2 = (const ulonglong2*)fsh;
#pragma unroll
            for (int kk = 0; kk < 10; kk++) {
                int kg = half * 10 + kk;
                ulonglong2 fa = fs2[kg * 4 + 0];
                ulonglong2 fb = fs2[kg * 4 + 1];
                ulonglong2 fc = fs2[kg * 4 + 2];
                ulonglong2 fd = fs2[kg * 4 + 3];
                unsigned long long wd = dupf(w1r[kk]);
                fma2(acc[0], fa.x, wd); fma2(acc[1], fa.y, wd);
                fma2(acc[2], fb.x, wd); fma2(acc[3], fb.y, wd);
                fma2(acc[4], fc.x, wd); fma2(acc[5], fc.y, wd);
                fma2(acc[6], fd.x, wd); fma2(acc[7], fd.y, wd);
            }
            float4* dst = (half == 0) ? A4 : B4;
            float v[P];
#pragma unroll
            for (int i = 0; i < 8; i++) unpack2(acc[i], v[2 * i], v[2 * i + 1]);
#pragma unroll
            for (int q = 0; q < 4; q++)
                dst[j * 4 + q] = make_float4(v[4 * q], v[4 * q + 1], v[4 * q + 2], v[4 * q + 3]);
        }
        __syncthreads();

        // --- combine 1: u = ssp(partA + partB), in place in bufA ([j][p]) ---
#pragma unroll
        for (int i = 0; i < 2; i++) {
            float4 a = A4[tid * 2 + i];
            float4 b = B4[tid * 2 + i];
            a.x = sspf(a.x + b.x);
            a.y = sspf(a.y + b.y);
            a.z = sspf(a.z + b.z);
            a.w = sspf(a.w + b.w);
            A4[tid * 2 + i] = a;
        }
        __syncthreads();

        // --- stage 2 partial: 64 k's per half, u broadcast from bufA ---
        {
            unsigned long long acc[8];
            unsigned long long bi = pack2(b2, b2);
#pragma unroll
            for (int i = 0; i < 8; i++) acc[i] = bi;
#pragma unroll
            for (int kk = 0; kk < 64; kk++) {
                int kg = half * 64 + kk;
                ulonglong2 ua = ((const ulonglong2*)bufA)[kg * 4 + 0];
                ulonglong2 ub = ((const ulonglong2*)bufA)[kg * 4 + 1];
                ulonglong2 uc = ((const ulonglong2*)bufA)[kg * 4 + 2];
                ulonglong2 ud = ((const ulonglong2*)bufA)[kg * 4 + 3];
                unsigned long long wd = dupf(w2r[kk]);
                fma2(acc[0], ua.x, wd); fma2(acc[1], ua.y, wd);
                fma2(acc[2], ub.x, wd); fma2(acc[3], ub.y, wd);
                fma2(acc[4], uc.x, wd); fma2(acc[5], uc.y, wd);
                fma2(acc[6], ud.x, wd); fma2(acc[7], ud.y, wd);
            }
            float4* dst = (half == 0) ? B4 : C4;
            float v[P];
#pragma unroll
            for (int i = 0; i < 8; i++) unpack2(acc[i], v[2 * i], v[2 * i + 1]);
#pragma unroll
            for (int q = 0; q < 4; q++)
                dst[j * 4 + q] = make_float4(v[4 * q], v[4 * q + 1], v[4 * q + 2], v[4 * q + 3]);
        }
        __syncthreads();

        // --- combine 2: w[p][jj] = (partB + partC) * rc[p]  -> bufA [p][j] ---
        {
            const int jj = tid >> 1;                 // column this thread finalizes
            const int pb = (tid & 1) * 8;            // pair base (0 or 8)
#pragma unroll
            for (int i = 0; i < 2; i++) {
                float4 b = B4[tid * 2 + i];
                float4 c = C4[tid * 2 + i];
                int pbase = pb + i * 4;
                bufA[(pbase + 0) * NB + jj] = (b.x + c.x) * rcsh[pbase + 0];
                bufA[(pbase + 1) * NB + jj] = (b.y + c.y) * rcsh[pbase + 1];
                bufA[(pbase + 2) * NB + jj] = (b.z + c.z) * rcsh[pbase + 2];
                bufA[(pbase + 3) * NB + jj] = (b.w + c.w) * rcsh[pbase + 3];
            }
        }
        __syncthreads();

        // --- epilogue: warp wid -> pairs p0, p1 ---
        {
            float4 wv0 = ((const float4*)(bufA + p0 * NB))[lane];
            red4(agg + (size_t)ii0 * NB + lane * 4,
                 wv0.x * hv0.x, wv0.y * hv0.y, wv0.z * hv0.z, wv0.w * hv0.w);
            float4 wv1 = ((const float4*)(bufA + p1 * NB))[lane];
            red4(agg + (size_t)ii1 * NB + lane * 4,
                 wv1.x * hv1.x, wv1.y * hv1.y, wv1.z * hv1.z, wv1.w * hv1.w);
        }
    }
}

// ---------------- launch ----------------
extern "C" void kernel_launch(void* const* d_in, const int* in_sizes, int n_in,
                              void* d_out, int out_size) {
    const float* x    = (const float*)d_in[0];
    const float* f_ij = (const float*)d_in[1];
    const float* rcut = (const float*)d_in[2];
    const float* W_in = (const float*)d_in[3];
    const float* b_in = (const float*)d_in[4];
    const float* Wf1  = (const float*)d_in[5];
    const float* bf1  = (const float*)d_in[6];
    const float* Wf2  = (const float*)d_in[7];
    const float* bf2  = (const float*)d_in[8];
    const float* Wo1  = (const float*)d_in[9];
    const float* bo1  = (const float*)d_in[10];
    const float* Wo2  = (const float*)d_in[11];
    const float* bo2  = (const float*)d_in[12];
    const int* idx_i  = (const int*)d_in[13];
    const int* idx_j  = (const int*)d_in[14];

    const int natoms = in_sizes[0] / NB;
    const int npairs = in_sizes[2];
    float* out = (float*)d_out;

    float *hp, *aggp, *tp;
    cudaGetSymbolAddress((void**)&hp, g_h);
    cudaGetSymbolAddress((void**)&aggp, g_agg);
    cudaGetSymbolAddress((void**)&tp, g_t);

    const int grid = 148 * 8;
    const int n4 = natoms * NB / 4;
    zero_kernel<<<(n4 + 255) / 256, 256>>>((float4*)aggp, n4);
    rowmm_kernel<false><<<grid, 128>>>(x, W_in, b_in, hp, natoms);
    dummy_kernel<<<1, 32>>>();
    pair_kernel<<<148 * 2, 256>>>(f_ij, rcut, Wf1, bf1, Wf2, bf2,
                                  idx_i, idx_j, hp, aggp, npairs);
    rowmm_kernel<true><<<grid, 128>>>(aggp, Wo1, bo1, tp, natoms);
    rowmm_kernel<false><<<grid, 128>>>(tp, Wo2, bo2, out, natoms);
}

// round 9
// speedup vs baseline: 2.7332x; 2.7332x over previous
#include <cuda_runtime.h>
#include <cstdint>

#define NB 128
#define TILE 64
#define N_ATOMS_MAX 50000

typedef unsigned long long ull;

// Scratch (device globals: allocation-free per harness rules)
__device__ float g_h[N_ATOMS_MAX * NB];
__device__ float g_agg[N_ATOMS_MAX * NB];
__device__ float g_t[N_ATOMS_MAX * NB];

// ---------------- helpers ----------------

__device__ __forceinline__ float sspf(float x) {
    float e = __expf(-fabsf(x));
    return fmaxf(x, 0.0f) + __logf(1.0f + e) - 0.69314718055994531f;
}
__device__ __forceinline__ ull pack2(float x, float y) {
    ull r; asm("mov.b64 %0, {%1, %2};" : "=l"(r) : "f"(x), "f"(y)); return r;
}
__device__ __forceinline__ ull dupf(float w) {
    ull r; asm("mov.b64 %0, {%1, %1};" : "=l"(r) : "f"(w)); return r;
}
__device__ __forceinline__ void unpack2(ull v, float& x, float& y) {
    asm("mov.b64 {%0, %1}, %2;" : "=f"(x), "=f"(y) : "l"(v));
}
__device__ __forceinline__ void fma2(ull& d, ull a, ull b) {
    asm("fma.rn.f32x2 %0, %1, %2, %3;" : "=l"(d) : "l"(a), "l"(b), "l"(d));
}
__device__ __forceinline__ void red4(float* p, float a, float b, float c, float d) {
    asm volatile("red.global.add.v4.f32 [%0], {%1,%2,%3,%4};"
                 :: "l"(p), "f"(a), "f"(b), "f"(c), "f"(d) : "memory");
}

// ---------------- zero / dummy ----------------
__global__ void zero_kernel(float4* __restrict__ p, int n4) {
    int i = blockIdx.x * blockDim.x + threadIdx.x;
    if (i < n4) p[i] = make_float4(0.f, 0.f, 0.f, 0.f);
}
__global__ void dummy_kernel() {}

// ---------------- row GEMM: Y = [ssp](X @ W + b), K=N=128 ----------------
template <bool DOSSP>
__global__ __launch_bounds__(128, 2) void rowmm_kernel(
    const float* __restrict__ X, const float* __restrict__ W,
    const float* __restrict__ b, float* __restrict__ Y, int nrows) {
    const int j = threadIdx.x;
    float wr[NB];
#pragma unroll
    for (int k = 0; k < NB; k++) wr[k] = W[k * NB + j];
    const float bj = b[j];
    __shared__ __align__(16) float xsh[NB * 4];
    const int ngroups = (nrows + 3) / 4;
    for (int g = blockIdx.x; g < ngroups; g += gridDim.x) {
        const int row0 = g * 4;
        __syncthreads();
#pragma unroll
        for (int r = 0; r < 4; r++) {
            int row = row0 + r;
            xsh[j * 4 + r] = (row < nrows) ? X[row * NB + j] : 0.0f;
        }
        __syncthreads();
        ull a01 = pack2(bj, bj), a23 = a01;
        const ulonglong2* xs2 = (const ulonglong2*)xsh;
#pragma unroll
        for (int k = 0; k < NB; k++) {
            ulonglong2 uv = xs2[k];
            ull wd = dupf(wr[k]);
            fma2(a01, uv.x, wd);
            fma2(a23, uv.y, wd);
        }
        float y0, y1, y2, y3;
        unpack2(a01, y0, y1); unpack2(a23, y2, y3);
        if (DOSSP) { y0 = sspf(y0); y1 = sspf(y1); y2 = sspf(y2); y3 = sspf(y3); }
        float yv[4] = {y0, y1, y2, y3};
#pragma unroll
        for (int r = 0; r < 4; r++) {
            int row = row0 + r;
            if (row < nrows) Y[row * NB + j] = yv[r];
        }
    }
}

// ---------------- pair kernel: 2D register tiling ----------------
// Tile = 64 pairs x 128 cols. Thread tile = 8 pairs x 4 cols (16 fma2 accums).
// Per k in stage 2: 2 broadcast LDS.128 (u, 8 pairs) + 1 LDS.128 (W2, 4 cols)
// feed 16 fma2. Wf2 resident in smem; u rows padded to 68 floats.

// smem float offsets
#define SM_W2   0                    // 128*128        = 16384
#define SM_F    16384                // 20*68          = 1360
#define SM_U    17744                // 128*68         = 8704  (union with w: 64*132=8448)
#define SM_II   26448                // 64
#define SM_IJ   26512                // 64
#define SM_RC   26576                // 64
#define SM_FLOATS 26640
#define SM_BYTES (SM_FLOATS * 4)

__global__ __launch_bounds__(256, 2) void pair_kernel(
    const float* __restrict__ f_ij, const float* __restrict__ rcut,
    const float* __restrict__ Wf1, const float* __restrict__ bf1,
    const float* __restrict__ Wf2, const float* __restrict__ bf2,
    const int* __restrict__ idx_i, const int* __restrict__ idx_j,
    const float* __restrict__ h, float* __restrict__ agg, int npairs) {
    extern __shared__ __align__(16) float sm[];
    float* W2s = sm + SM_W2;
    float* fs  = sm + SM_F;
    float* us  = sm + SM_U;
    float* ws  = sm + SM_U;   // union: written after all u reads complete
    int*   iis = (int*)(sm + SM_II);
    int*   ijs = (int*)(sm + SM_IJ);
    float* rcs = sm + SM_RC;

    const int tid  = threadIdx.x;
    const int wid  = tid >> 5;
    const int lane = tid & 31;
    const int j2   = tid & 127;     // stage-1 column
    const int ph   = tid >> 7;      // stage-1 pair half (32 pairs each)

    // persistent: Wf2 -> smem, Wf1 column -> regs
    for (int i = tid * 4; i < NB * NB; i += 1024)
        *(float4*)(W2s + i) = *(const float4*)(Wf2 + i);
    float w1r[20];
#pragma unroll
    for (int k = 0; k < 20; k++) w1r[k] = Wf1[k * NB + j2];
    const float b1 = bf1[j2];

    // stage-2 thread tile: 8 pairs (pr0..) x 4 cols (c0..)
    const int colg  = ((wid & 3) << 3) + (lane & 7);   // 0..31
    const int c0    = colg << 2;
    const int pairg = ((wid >> 2) << 2) + (lane >> 3); // 0..7
    const int pr0   = pairg << 3;
    const float4 b2v = *(const float4*)(bf2 + c0);
    const ull bd0 = dupf(b2v.x), bd1 = dupf(b2v.y), bd2 = dupf(b2v.z), bd3 = dupf(b2v.w);

    const int ntiles = (npairs + TILE - 1) / TILE;
    for (int t = blockIdx.x; t < ntiles; t += gridDim.x) {
        const int base = t * TILE;
        __syncthreads();  // prev epilogue reads of ws done

        // --- f tile load + transpose to fs[k][p] ---
        if (base + TILE <= npairs) {
            for (int vi = tid; vi < TILE * 5; vi += 256) {
                float4 v = ((const float4*)f_ij)[base * 5 + vi];
                int g = vi * 4;
                int p = g / 20, k = g - p * 20;  // k in {0,4,8,12,16}: no row wrap
                fs[(k + 0) * 68 + p] = v.x;
                fs[(k + 1) * 68 + p] = v.y;
                fs[(k + 2) * 68 + p] = v.z;
                fs[(k + 3) * 68 + p] = v.w;
            }
        } else {
            for (int vi = tid; vi < TILE * 20; vi += 256) {
                int p = vi / 20, k = vi - p * 20;
                int e = base + p;
                fs[k * 68 + p] = (e < npairs) ? f_ij[e * 20 + k] : 0.0f;
            }
        }
        if (tid < TILE) {
            int e = base + tid;
            bool v = (e < npairs);
            iis[tid] = v ? idx_i[e] : 0;
            ijs[tid] = v ? idx_j[e] : 0;
            rcs[tid] = v ? rcut[e] : 0.0f;
        }
        __syncthreads();

        // --- stage 1: u[j2][ph*32..+32] = ssp(f @ Wf1[:,j2] + b1) ---
        {
            ull a[16];
            ull bi = pack2(b1, b1);
#pragma unroll
            for (int i = 0; i < 16; i++) a[i] = bi;
#pragma unroll
            for (int k = 0; k < 20; k++) {
                const ulonglong2* fp = (const ulonglong2*)(fs + k * 68 + (ph << 5));
                ull wd = dupf(w1r[k]);
#pragma unroll
                for (int q = 0; q < 8; q++) {
                    ulonglong2 fv = fp[q];
                    fma2(a[2 * q], fv.x, wd);
                    fma2(a[2 * q + 1], fv.y, wd);
                }
            }
            float v[32];
#pragma unroll
            for (int i = 0; i < 16; i++) unpack2(a[i], v[2 * i], v[2 * i + 1]);
#pragma unroll
            for (int i = 0; i < 32; i++) v[i] = sspf(v[i]);
#pragma unroll
            for (int q = 0; q < 8; q++)
                *(float4*)(us + j2 * 68 + (ph << 5) + q * 4) =
                    make_float4(v[4 * q], v[4 * q + 1], v[4 * q + 2], v[4 * q + 3]);
        }
        __syncthreads();

        // --- stage 2: acc[8 pairs][4 cols] = u @ Wf2 + bf2 ---
        ull acc[16];
#pragma unroll
        for (int pp = 0; pp < 4; pp++) {
            acc[pp * 4 + 0] = bd0; acc[pp * 4 + 1] = bd1;
            acc[pp * 4 + 2] = bd2; acc[pp * 4 + 3] = bd3;
        }
        {
            const float* upb = us + pr0;
            const float* wpb = W2s + c0;
#pragma unroll 8
            for (int k = 0; k < NB; k++) {
                const ulonglong2* up = (const ulonglong2*)(upb + k * 68);
                ulonglong2 ua = up[0], ub = up[1];         // 8 pairs of u[k]
                float4 wv = *(const float4*)(wpb + (k << 7));
                ull w0 = dupf(wv.x), w1 = dupf(wv.y), w2 = dupf(wv.z), w3 = dupf(wv.w);
                fma2(acc[0],  ua.x, w0); fma2(acc[1],  ua.x, w1);
                fma2(acc[2],  ua.x, w2); fma2(acc[3],  ua.x, w3);
                fma2(acc[4],  ua.y, w0); fma2(acc[5],  ua.y, w1);
                fma2(acc[6],  ua.y, w2); fma2(acc[7],  ua.y, w3);
                fma2(acc[8],  ub.x, w0); fma2(acc[9],  ub.x, w1);
                fma2(acc[10], ub.x, w2); fma2(acc[11], ub.x, w3);
                fma2(acc[12], ub.y, w0); fma2(acc[13], ub.y, w1);
                fma2(acc[14], ub.y, w2); fma2(acc[15], ub.y, w3);
            }
        }
        __syncthreads();  // all u reads done; ws aliases us

        // --- transpose w (+rcut) into ws[p][j], rows padded to 132 ---
#pragma unroll
        for (int pp = 0; pp < 4; pp++) {
            int p_lo = pr0 + 2 * pp, p_hi = p_lo + 1;
            float rl = rcs[p_lo], rh = rcs[p_hi];
            float lo[4], hi[4];
#pragma unroll
            for (int q = 0; q < 4; q++) unpack2(acc[pp * 4 + q], lo[q], hi[q]);
            *(float4*)(ws + p_lo * 132 + c0) =
                make_float4(lo[0] * rl, lo[1] * rl, lo[2] * rl, lo[3] * rl);
            *(float4*)(ws + p_hi * 132 + c0) =
                make_float4(hi[0] * rh, hi[1] * rh, hi[2] * rh, hi[3] * rh);
        }
        __syncthreads();

        // --- epilogue: warp wid -> pairs wid*8..+8 (2 batches of 4) ---
#pragma unroll
        for (int bb = 0; bb < 2; bb++) {
            int pb = wid * 8 + bb * 4;
            float4 hv[4], wv4[4];
            int iv[4];
#pragma unroll
            for (int q = 0; q < 4; q++) {
                int p = pb + q;
                int ij = ijs[p];
                iv[q] = iis[p];
                hv[q]  = *(const float4*)(h + (size_t)ij * NB + lane * 4);
                wv4[q] = *(const float4*)(ws + p * 132 + lane * 4);
            }
#pragma unroll
            for (int q = 0; q < 4; q++)
                red4(agg + (size_t)iv[q] * NB + lane * 4,
                     wv4[q].x * hv[q].x, wv4[q].y * hv[q].y,
                     wv4[q].z * hv[q].z, wv4[q].w * hv[q].w);
        }
    }
}

// ---------------- launch ----------------
extern "C" void kernel_launch(void* const* d_in, const int* in_sizes, int n_in,
                              void* d_out, int out_size) {
    const float* x    = (const float*)d_in[0];
    const float* f_ij = (const float*)d_in[1];
    const float* rcut = (const float*)d_in[2];
    const float* W_in = (const float*)d_in[3];
    const float* b_in = (const float*)d_in[4];
    const float* Wf1  = (const float*)d_in[5];
    const float* bf1  = (const float*)d_in[6];
    const float* Wf2  = (const float*)d_in[7];
    const float* bf2  = (const float*)d_in[8];
    const float* Wo1  = (const float*)d_in[9];
    const float* bo1  = (const float*)d_in[10];
    const float* Wo2  = (const float*)d_in[11];
    const float* bo2  = (const float*)d_in[12];
    const int* idx_i  = (const int*)d_in[13];
    const int* idx_j  = (const int*)d_in[14];

    const int natoms = in_sizes[0] / NB;
    const int npairs = in_sizes[2];
    float* out = (float*)d_out;

    float *hp, *aggp, *tp;
    cudaGetSymbolAddress((void**)&hp, g_h);
    cudaGetSymbolAddress((void**)&aggp, g_agg);
    cudaGetSymbolAddress((void**)&tp, g_t);

    // one-time opt-in for >48KB dynamic smem (runs on the uncaptured correctness call)
    static const bool once = []() {
        cudaFuncSetAttribute(pair_kernel,
                             cudaFuncAttributeMaxDynamicSharedMemorySize, SM_BYTES);
        return true;
    }();
    (void)once;

    const int grid = 148 * 8;
    const int n4 = natoms * NB / 4;
    zero_kernel<<<(n4 + 255) / 256, 256>>>((float4*)aggp, n4);
    rowmm_kernel<false><<<grid, 128>>>(x, W_in, b_in, hp, natoms);
    dummy_kernel<<<1, 32>>>();
    pair_kernel<<<148 * 2, 256, SM_BYTES>>>(f_ij, rcut, Wf1, bf1, Wf2, bf2,
                                            idx_i, idx_j, hp, aggp, npairs);
    rowmm_kernel<true><<<grid, 128>>>(aggp, Wo1, bo1, tp, natoms);
    rowmm_kernel<false><<<grid, 128>>>(tp, Wo2, bo2, out, natoms);
}